// round 6
// baseline (speedup 1.0000x reference)
#include <cuda_runtime.h>
#include <math.h>

#define BB 8
#define NN 16384
#define DD 128
#define OO 256
#define CH1 448
#define NCH 37
#define LN_EPS 1e-5f
#define QP 66
#define K3_SMEM ((32768 + DD*QP) * 4)

typedef unsigned long long u64;

__device__ float g_ctx_part[(size_t)BB * NCH * DD * DD]; // ~19.4MB
__device__ float g_ksum_part[(size_t)BB * NCH * DD];
__device__ float g_wT[DD * OO];
__device__ float g_M[(size_t)BB * DD * OO];

__device__ __forceinline__ u64 splat2(float a) {
    u64 r; unsigned int ai = __float_as_uint(a);
    asm("mov.b64 %0, {%1, %1};" : "=l"(r) : "r"(ai));
    return r;
}
__device__ __forceinline__ void ffma2(u64 &d, u64 a, u64 b) {
    asm("fma.rn.f32x2 %0, %1, %2, %0;" : "+l"(d) : "l"(a), "l"(b));
}
__device__ __forceinline__ u64 add2(u64 a, u64 b) {
    u64 r; asm("add.rn.f32x2 %0, %1, %2;" : "=l"(r) : "l"(a), "l"(b));
    return r;
}
__device__ __forceinline__ float2 unpack2(u64 v) {
    unsigned int lo, hi;
    asm("mov.b64 {%0, %1}, %2;" : "=r"(lo), "=r"(hi) : "l"(v));
    return make_float2(__uint_as_float(lo), __uint_as_float(hi));
}

// ---------------- K0: transpose W[256,128] -> wT[128,256] ----------------
__global__ void k0_transpose(const float* __restrict__ w) {
    int i = blockIdx.x * blockDim.x + threadIdx.x;
    if (i < DD * OO) { int o = i / DD, v = i % DD; g_wT[v * OO + o] = w[i]; }
}

// ---------------- K1: context partials + column exp-sums ----------------
__global__ void __launch_bounds__(256, 2) k1_context(const float* __restrict__ x1,
                                                     const float* __restrict__ x2) {
    __shared__ __align__(16) float Es[2][8][132];
    __shared__ __align__(16) float Xs[2][8][132];
    __shared__ float csum_s[8][128];

    const int b = blockIdx.y, ch = blockIdx.x;
    const int n0 = ch * CH1;
    const int nrows = (NN - n0 < CH1) ? (NN - n0) : CH1;
    const int nit = nrows >> 3;

    const int t = threadIdx.x;
    const int lrow = t >> 5, lq = t & 31;
    const int ty = t >> 4, tx = t & 15;
    const int ldidx = lrow * 32 + lq;

    const float4* x1p = (const float4*)(x1 + ((size_t)b * NN + n0) * DD);
    const float4* x2p = (const float4*)(x2 + ((size_t)b * NN + n0) * DD);

    u64 acc[8][4];
#pragma unroll
    for (int i = 0; i < 8; ++i)
#pragma unroll
        for (int j = 0; j < 4; ++j) acc[i][j] = 0ull;

    float4 cs = make_float4(0.f, 0.f, 0.f, 0.f);
    float4 ra = x1p[ldidx];
    float4 rb = x2p[ldidx];

    for (int it = 0; it < nit; ++it) {
        const int buf = it & 1;
        float4 ea;
        ea.x = __expf(ra.x); ea.y = __expf(ra.y); ea.z = __expf(ra.z); ea.w = __expf(ra.w);
        cs.x += ea.x; cs.y += ea.y; cs.z += ea.z; cs.w += ea.w;
        *(float4*)&Es[buf][lrow][lq * 4] = ea;
        *(float4*)&Xs[buf][lrow][lq * 4] = rb;
        __syncthreads();
        if (it + 1 < nit) {
            ra = x1p[(it + 1) * 256 + ldidx];
            rb = x2p[(it + 1) * 256 + ldidx];
        }
#pragma unroll
        for (int r = 0; r < 8; ++r) {
            const float* er = &Es[buf][r][0];
            const float* xr = &Xs[buf][r][0];
            float a[8];
            *(float4*)&a[0] = *(const float4*)(er + 4 * ty);
            *(float4*)&a[4] = *(const float4*)(er + 64 + 4 * ty);
            ulonglong2 b0 = *(const ulonglong2*)(xr + 4 * tx);
            ulonglong2 b1 = *(const ulonglong2*)(xr + 64 + 4 * tx);
#pragma unroll
            for (int i = 0; i < 8; ++i) {
                u64 s = splat2(a[i]);
                ffma2(acc[i][0], s, b0.x);
                ffma2(acc[i][1], s, b0.y);
                ffma2(acc[i][2], s, b1.x);
                ffma2(acc[i][3], s, b1.y);
            }
        }
    }

    *(float4*)&csum_s[lrow][lq * 4] = cs;
    __syncthreads();
    if (t < 128) {
        float s = 0.f;
#pragma unroll
        for (int g = 0; g < 8; ++g) s += csum_s[g][t];
        g_ksum_part[((size_t)b * NCH + ch) * DD + t] = s;
    }

    float* outp = g_ctx_part + ((size_t)b * NCH + ch) * DD * DD;
#pragma unroll
    for (int i = 0; i < 8; ++i) {
        const int d = (i < 4) ? (4 * ty + i) : (64 + 4 * ty + (i - 4));
        float* rowp = outp + (size_t)d * DD;
        ulonglong2 s01; s01.x = acc[i][0]; s01.y = acc[i][1];
        ulonglong2 s23; s23.x = acc[i][2]; s23.y = acc[i][3];
        *(ulonglong2*)(rowp + 4 * tx)      = s01;
        *(ulonglong2*)(rowp + 64 + 4 * tx) = s23;
    }
}

// ---------------- K2: merge partials, normalize, M = ctx_norm @ W^T ----------------
__global__ void k2_M() {
    __shared__ float ctx_s[4][128];
    __shared__ float ks_s[4];
    const int b = blockIdx.y, dg = blockIdx.x;
    const int t = threadIdx.x;

    if (t < 4) {
        float s = 0.f;
        for (int ch = 0; ch < NCH; ++ch)
            s += g_ksum_part[((size_t)b * NCH + ch) * DD + dg * 4 + t];
        ks_s[t] = 1.0f / s;
    }
    __syncthreads();

    for (int e = t; e < 512; e += 256) {
        const int d = e >> 7, v = e & 127;
        const float* p = g_ctx_part + (size_t)b * NCH * DD * DD + (size_t)(dg * 4 + d) * DD + v;
        float s = 0.f;
        for (int ch = 0; ch < NCH; ++ch) s += p[(size_t)ch * DD * DD];
        ctx_s[d][v] = s * ks_s[d];
    }
    __syncthreads();

    float a0 = 0.f, a1 = 0.f, a2 = 0.f, a3 = 0.f;
#pragma unroll 8
    for (int v = 0; v < 128; ++v) {
        const float wv = g_wT[v * OO + t];
        a0 = fmaf(ctx_s[0][v], wv, a0);
        a1 = fmaf(ctx_s[1][v], wv, a1);
        a2 = fmaf(ctx_s[2][v], wv, a2);
        a3 = fmaf(ctx_s[3][v], wv, a3);
    }
    float* Mp = g_M + ((size_t)b * DD + dg * 4) * OO + t;
    Mp[0] = a0; Mp[OO] = a1; Mp[2 * OO] = a2; Mp[3 * OO] = a3;
}

// ---------------- K3: eff = softmax_D(x1) @ M + bias, fused LayerNorm ----------------
__global__ void __launch_bounds__(256, 1) k3_final(const float* __restrict__ x1,
                                                   const float* __restrict__ bias,
                                                   const float* __restrict__ gamma,
                                                   const float* __restrict__ beta,
                                                   float* __restrict__ out) {
    extern __shared__ float sm[];
    float* M_s = sm;            // 32768 floats
    float* q_s = sm + 32768;    // 128 * QP

    const int t = threadIdx.x;
    const int lane = t & 31, g = t >> 5;

    // per-thread constants (outputs o = lane + 32*j)
    float gam[8], bet[8], bia[8];
#pragma unroll
    for (int j = 0; j < 8; ++j) {
        gam[j] = gamma[lane + 32 * j];
        bet[j] = beta[lane + 32 * j];
        bia[j] = bias[lane + 32 * j];
    }

    const int TILES = BB * (NN / 64); // 2048
    const int start = (blockIdx.x * TILES) / gridDim.x;
    const int end   = ((blockIdx.x + 1) * TILES) / gridDim.x;
    int curb = -1;

    for (int tile = start; tile < end; ++tile) {
        const int b = tile >> 8;
        const int n0 = (tile & 255) * 64;

        if (b != curb) {
            __syncthreads();
            const float4* Mp = (const float4*)(g_M + (size_t)b * DD * OO);
            for (int i = t; i < 8192; i += 256) ((float4*)M_s)[i] = Mp[i];
            curb = b;
            __syncthreads();
        }

        // --- q for this warp's 8 rows (softmax over D) ---
#pragma unroll
        for (int j = 0; j < 8; ++j) {
            const int r = g * 8 + j;
            const float4 v = ((const float4*)(x1 + ((size_t)b * NN + n0 + r) * DD))[lane];
            float e0 = __expf(v.x), e1 = __expf(v.y), e2 = __expf(v.z), e3 = __expf(v.w);
            float s = e0 + e1 + e2 + e3;
#pragma unroll
            for (int m = 16; m; m >>= 1) s += __shfl_xor_sync(0xffffffffu, s, m);
            const float inv = 1.0f / s;
            q_s[(4 * lane + 0) * QP + r] = e0 * inv;
            q_s[(4 * lane + 1) * QP + r] = e1 * inv;
            q_s[(4 * lane + 2) * QP + r] = e2 * inv;
            q_s[(4 * lane + 3) * QP + r] = e3 * inv;
        }
        __syncwarp();

        // --- GEMM: acc[j][p] = rows (g*8+2p, +1) at output lane+32j ---
        u64 acc[8][4];
#pragma unroll
        for (int j = 0; j < 8; ++j)
#pragma unroll
            for (int p = 0; p < 4; ++p) acc[j][p] = 0ull;

        for (int d = 0; d < 128; ++d) {
            const float* qd = q_s + d * QP + g * 8;
            const u64 q0 = *(const u64*)(qd + 0);
            const u64 q1 = *(const u64*)(qd + 2);
            const u64 q2 = *(const u64*)(qd + 4);
            const u64 q3 = *(const u64*)(qd + 6);
            const float* md = M_s + d * OO + lane;
#pragma unroll
            for (int j = 0; j < 8; ++j) {
                const u64 s = splat2(md[32 * j]);
                ffma2(acc[j][0], q0, s);
                ffma2(acc[j][1], q1, s);
                ffma2(acc[j][2], q2, s);
                ffma2(acc[j][3], q3, s);
            }
        }

        // bias
#pragma unroll
        for (int j = 0; j < 8; ++j) {
            const u64 bb = splat2(bia[j]);
#pragma unroll
            for (int p = 0; p < 4; ++p) acc[j][p] = add2(acc[j][p], bb);
        }

        // LayerNorm + store, per row-pair
#pragma unroll
        for (int p = 0; p < 4; ++p) {
            u64 s = 0ull, ss = 0ull;
#pragma unroll
            for (int j = 0; j < 8; ++j) {
                const u64 v = acc[j][p];
                s = add2(s, v);
                ffma2(ss, v, v);
            }
#pragma unroll
            for (int m = 16; m; m >>= 1) {
                s  = add2(s,  __shfl_xor_sync(0xffffffffu, s,  m));
                ss = add2(ss, __shfl_xor_sync(0xffffffffu, ss, m));
            }
            const float2 sf = unpack2(s), ssf = unpack2(ss);
            const float mean0 = sf.x * 0.00390625f, mean1 = sf.y * 0.00390625f;
            const float r0std = rsqrtf(ssf.x * 0.00390625f - mean0 * mean0 + LN_EPS);
            const float r1std = rsqrtf(ssf.y * 0.00390625f - mean1 * mean1 + LN_EPS);
            const int row = n0 + g * 8 + 2 * p;
            float* o0 = out + ((size_t)b * NN + row) * OO + lane;
            float* o1 = o0 + OO;
#pragma unroll
            for (int j = 0; j < 8; ++j) {
                const float2 v = unpack2(acc[j][p]);
                o0[32 * j] = (v.x - mean0) * r0std * gam[j] + bet[j];
                o1[32 * j] = (v.y - mean1) * r1std * gam[j] + bet[j];
            }
        }
        __syncwarp();
    }
}

extern "C" void kernel_launch(void* const* d_in, const int* in_sizes, int n_in,
                              void* d_out, int out_size) {
    const float* x1  = (const float*)d_in[0];
    const float* x2  = (const float*)d_in[1];
    const float* w   = (const float*)d_in[2];
    const float* brp = (const float*)d_in[3];
    const float* gam = (const float*)d_in[4];
    const float* bet = (const float*)d_in[5];
    float* out = (float*)d_out;

    cudaFuncSetAttribute(k3_final, cudaFuncAttributeMaxDynamicSharedMemorySize, K3_SMEM);

    k0_transpose<<<128, 256>>>(w);
    k1_context<<<dim3(NCH, BB), 256>>>(x1, x2);
    k2_M<<<dim3(32, BB), 256>>>();
    k3_final<<<148, 256, K3_SMEM>>>(x1, brp, gam, bet, out);
}